// round 1
// baseline (speedup 1.0000x reference)
#include <cuda_runtime.h>
#include <math.h>

#define Bb 2
#define Ss 1024
#define Tt 2048
#define Dd 2048
#define Ll 4
#define NE 16
#define Hh 16
#define DHh 128
#define CAPe 153

// ---------------- scratch (static device globals; no allocations) ----------
__device__ float g_x[Tt * Dd];          // residual stream
__device__ float g_xn[Tt * Dd];         // LN output
__device__ float g_qkv[Tt * 3 * Dd];    // qkv projections
__device__ float g_attn[Tt * Dd];       // attention output
__device__ int   g_expert[Tt];
__device__ float g_prob[Tt];
__device__ float g_probsum[NE];
__device__ int   g_tok[NE * CAPe];
__device__ int   g_cnt[NE];
__device__ float g_aux;

// ---------------- init -----------------------------------------------------
__global__ void k_init() { g_aux = 0.0f; }

__global__ void k_zero16() { if (threadIdx.x < NE) g_probsum[threadIdx.x] = 0.0f; }

// ---------------- embedding gather ------------------------------------------
__global__ void k_embed(const int* __restrict__ tokens, const float* __restrict__ emb) {
    int idx = blockIdx.x * 256 + threadIdx.x;
    int t = idx / Dd;
    int d = idx % Dd;
    g_x[idx] = emb[(size_t)tokens[t] * Dd + d];
}

// ---------------- layernorm (block per row) ---------------------------------
__global__ void k_ln(const float* __restrict__ gamma, const float* __restrict__ beta) {
    int t = blockIdx.x;
    const float* row = g_x + (size_t)t * Dd;
    float s = 0.f, s2 = 0.f;
    for (int d = threadIdx.x; d < Dd; d += 256) {
        float v = row[d];
        s += v; s2 += v * v;
    }
    #pragma unroll
    for (int o = 16; o; o >>= 1) {
        s  += __shfl_xor_sync(0xffffffffu, s, o);
        s2 += __shfl_xor_sync(0xffffffffu, s2, o);
    }
    __shared__ float shs[8], shs2[8];
    __shared__ float smu, srstd;
    int w = threadIdx.x >> 5, ln = threadIdx.x & 31;
    if (ln == 0) { shs[w] = s; shs2[w] = s2; }
    __syncthreads();
    if (threadIdx.x == 0) {
        float a = 0.f, b2 = 0.f;
        #pragma unroll
        for (int i = 0; i < 8; i++) { a += shs[i]; b2 += shs2[i]; }
        float m = a / (float)Dd;
        float var = b2 / (float)Dd - m * m;
        smu = m;
        srstd = rsqrtf(var + 1e-5f);
    }
    __syncthreads();
    float mu = smu, rstd = srstd;
    for (int d = threadIdx.x; d < Dd; d += 256)
        g_xn[(size_t)t * Dd + d] = (row[d] - mu) * rstd * gamma[d] + beta[d];
}

// ---------------- generic GEMM: C = A[MxK] * W[NxK]^T + bias (+res) --------
// BM=128, BN=64, BK=16, 256 threads, TM=8, TN=4
__global__ void k_gemm(const float* __restrict__ A, const float* __restrict__ W,
                       const float* __restrict__ bias, const float* __restrict__ res,
                       float* __restrict__ C, int M, int N, int K) {
    __shared__ float As[16][132];
    __shared__ float Ws[16][68];
    int bm = blockIdx.y * 128, bn = blockIdx.x * 64;
    int tid = threadIdx.x;
    int ty = tid >> 4, tx = tid & 15;
    float acc[8][4];
    #pragma unroll
    for (int i = 0; i < 8; i++)
        #pragma unroll
        for (int j = 0; j < 4; j++) acc[i][j] = 0.f;

    for (int k0 = 0; k0 < K; k0 += 16) {
        #pragma unroll
        for (int i = 0; i < 2; i++) {
            int lin = tid + i * 256;           // 512 float4 = 2048 floats
            int r = lin >> 2;
            int kq = (lin & 3) << 2;
            float4 v = *(const float4*)(A + (size_t)(bm + r) * K + k0 + kq);
            As[kq + 0][r] = v.x; As[kq + 1][r] = v.y;
            As[kq + 2][r] = v.z; As[kq + 3][r] = v.w;
        }
        {
            int r = tid >> 2;
            int kq = (tid & 3) << 2;
            float4 v = *(const float4*)(W + (size_t)(bn + r) * K + k0 + kq);
            Ws[kq + 0][r] = v.x; Ws[kq + 1][r] = v.y;
            Ws[kq + 2][r] = v.z; Ws[kq + 3][r] = v.w;
        }
        __syncthreads();
        #pragma unroll
        for (int kk = 0; kk < 16; kk++) {
            float a[8], b[4];
            const float4* ap = (const float4*)&As[kk][ty * 8];
            float4 a0 = ap[0], a1 = ap[1];
            a[0]=a0.x; a[1]=a0.y; a[2]=a0.z; a[3]=a0.w;
            a[4]=a1.x; a[5]=a1.y; a[6]=a1.z; a[7]=a1.w;
            float4 b0 = *(const float4*)&Ws[kk][tx * 4];
            b[0]=b0.x; b[1]=b0.y; b[2]=b0.z; b[3]=b0.w;
            #pragma unroll
            for (int i = 0; i < 8; i++)
                #pragma unroll
                for (int j = 0; j < 4; j++) acc[i][j] += a[i] * b[j];
        }
        __syncthreads();
    }
    #pragma unroll
    for (int i = 0; i < 8; i++) {
        int r = bm + ty * 8 + i;
        #pragma unroll
        for (int j = 0; j < 4; j++) {
            int c = bn + tx * 4 + j;
            float v = acc[i][j] + bias[c];
            if (res) v += res[(size_t)r * N + c];
            C[(size_t)r * N + c] = v;
        }
    }
}

// ---------------- attention (flash-style, BQ=32, BKV=16) --------------------
__global__ void k_attn() {
    int bh = blockIdx.x;
    int b = bh >> 4, h = bh & 15;
    int q0 = blockIdx.y * 32;
    __shared__ float Qs[32][132];
    __shared__ float Ks[16][132];
    __shared__ float Vs[16][132];
    __shared__ float Sc[32][17];
    int tid = threadIdx.x;

    for (int i = tid; i < 32 * DHh; i += 256) {
        int r = i >> 7, d = i & 127;
        Qs[r][d] = g_qkv[(size_t)(b * Ss + q0 + r) * (3 * Dd) + h * DHh + d];
    }
    int q = tid >> 3;     // 0..31
    int dp = tid & 7;     // d-range dp*16 .. +16
    float m = -1e30f, l = 0.f;
    float acc[16];
    #pragma unroll
    for (int j = 0; j < 16; j++) acc[j] = 0.f;

    const float scale = 0.08838834764831845f;  // 1/sqrt(128)

    for (int kb = 0; kb < Ss; kb += 16) {
        __syncthreads();
        for (int i = tid; i < 16 * DHh; i += 256) {
            int r = i >> 7, d = i & 127;
            size_t base = (size_t)(b * Ss + kb + r) * (3 * Dd) + h * DHh + d;
            Ks[r][d] = g_qkv[base + Dd];
            Vs[r][d] = g_qkv[base + 2 * Dd];
        }
        __syncthreads();
        // scores: 2 per thread
        {
            int k2 = (tid & 7) * 2;
            #pragma unroll
            for (int kk = 0; kk < 2; kk++) {
                const float4* qp = (const float4*)&Qs[q][0];
                const float4* kp = (const float4*)&Ks[k2 + kk][0];
                float s = 0.f;
                #pragma unroll
                for (int d4 = 0; d4 < 32; d4++) {
                    float4 a = qp[d4], c = kp[d4];
                    s += a.x * c.x + a.y * c.y + a.z * c.z + a.w * c.w;
                }
                Sc[q][k2 + kk] = s * scale;
            }
        }
        __syncthreads();
        float mx = -1e30f;
        #pragma unroll
        for (int k = 0; k < 16; k++) mx = fmaxf(mx, Sc[q][k]);
        float nm = fmaxf(m, mx);
        float corr = __expf(m - nm);
        l *= corr;
        #pragma unroll
        for (int j = 0; j < 16; j++) acc[j] *= corr;
        #pragma unroll
        for (int k = 0; k < 16; k++) {
            float p = __expf(Sc[q][k] - nm);
            l += p;
            const float4* vp = (const float4*)&Vs[k][dp * 16];
            #pragma unroll
            for (int j4 = 0; j4 < 4; j4++) {
                float4 v = vp[j4];
                acc[j4 * 4 + 0] += p * v.x;
                acc[j4 * 4 + 1] += p * v.y;
                acc[j4 * 4 + 2] += p * v.z;
                acc[j4 * 4 + 3] += p * v.w;
            }
        }
        m = nm;
    }
    float inv = 1.f / l;
    int t = b * Ss + q0 + q;
    float* op = g_attn + (size_t)t * Dd + h * DHh + dp * 16;
    #pragma unroll
    for (int j = 0; j < 16; j++) op[j] = acc[j] * inv;
}

// ---------------- gate: softmax over 16 experts, warp per token -------------
__global__ void k_gate(const float* __restrict__ wg) {
    int warp = threadIdx.x >> 5;
    int lane = threadIdx.x & 31;
    int t = blockIdx.x * 8 + warp;
    __shared__ float bsum[NE];
    if (threadIdx.x < NE) bsum[threadIdx.x] = 0.f;
    __syncthreads();

    float lg[16];
    #pragma unroll
    for (int e = 0; e < 16; e++) lg[e] = 0.f;
    const float* row = g_xn + (size_t)t * Dd;
    for (int d = lane; d < Dd; d += 32) {
        float x = row[d];
        const float* w = wg + (size_t)d * NE;
        #pragma unroll
        for (int e = 0; e < 16; e++) lg[e] += x * w[e];
    }
    #pragma unroll
    for (int e = 0; e < 16; e++)
        #pragma unroll
        for (int o = 16; o; o >>= 1) lg[e] += __shfl_xor_sync(0xffffffffu, lg[e], o);

    float mx = lg[0];
    #pragma unroll
    for (int e = 1; e < 16; e++) mx = fmaxf(mx, lg[e]);
    float pe[16]; float se = 0.f;
    #pragma unroll
    for (int e = 0; e < 16; e++) { pe[e] = __expf(lg[e] - mx); se += pe[e]; }
    float inv = 1.f / se;

    if (lane == 0) {
        int be = 0; float bl = lg[0];
        #pragma unroll
        for (int e = 1; e < 16; e++) if (lg[e] > bl) { bl = lg[e]; be = e; }
        g_expert[t] = be;
        g_prob[t] = pe[be] * inv;
        #pragma unroll
        for (int e = 0; e < 16; e++) atomicAdd(&bsum[e], pe[e] * inv);
    }
    __syncthreads();
    if (threadIdx.x < NE) atomicAdd(&g_probsum[threadIdx.x], bsum[threadIdx.x]);
}

// ---------------- routing: token-order rank within expert, cap, aux ---------
__global__ void k_route() {
    __shared__ int sh_e[Tt];
    __shared__ int cnts[256][NE];
    __shared__ int tot[NE];
    int tid = threadIdx.x;
    for (int i = tid; i < Tt; i += 256) sh_e[i] = g_expert[i];
    #pragma unroll
    for (int e = 0; e < NE; e++) cnts[tid][e] = 0;
    __syncthreads();
    for (int i = 0; i < 8; i++) {
        int e = sh_e[tid * 8 + i];
        cnts[tid][e]++;
    }
    __syncthreads();
    if (tid < NE) {
        int run = 0;
        for (int i = 0; i < 256; i++) {
            int c = cnts[i][tid];
            cnts[i][tid] = run;
            run += c;
        }
        tot[tid] = run;
        g_cnt[tid] = (run < CAPe) ? run : CAPe;
    }
    __syncthreads();
    for (int i = 0; i < 8; i++) {
        int t = tid * 8 + i;
        int e = sh_e[t];
        int r = cnts[tid][e]++;
        if (r < CAPe) g_tok[e * CAPe + r] = t;
    }
    if (tid == 0) {
        float a = 0.f;
        for (int e = 0; e < NE; e++) a += (float)tot[e] * g_probsum[e];
        g_aux += a * ((float)NE / ((float)Tt * (float)Tt));
    }
}

// ---------------- MoE expert GEMM with gather/scatter, x += p*(h@W^T+b) -----
// BM=64, BN=64, BK=16, 256 threads, TM=4, TN=4
__global__ void k_moe(const float* __restrict__ w_exp, const float* __restrict__ b_exp) {
    int e = blockIdx.z;
    int cnt = g_cnt[e];
    int row0 = blockIdx.y * 64;
    if (row0 >= cnt) return;
    int bn = blockIdx.x * 64;
    int tid = threadIdx.x;

    __shared__ int   toks[64];
    __shared__ float pb[64];
    __shared__ float As[16][68];
    __shared__ float Ws[16][68];

    if (tid < 64) {
        int s = row0 + tid;
        if (s < cnt) {
            int t = g_tok[e * CAPe + s];
            toks[tid] = t;
            pb[tid] = g_prob[t];
        } else {
            toks[tid] = -1;
            pb[tid] = 0.f;
        }
    }
    __syncthreads();

    int ty = tid >> 4, tx = tid & 15;
    float acc[4][4];
    #pragma unroll
    for (int i = 0; i < 4; i++)
        #pragma unroll
        for (int j = 0; j < 4; j++) acc[i][j] = 0.f;

    const float* W = w_exp + (size_t)e * Dd * Dd;

    for (int k0 = 0; k0 < Dd; k0 += 16) {
        {
            int r = tid >> 2;
            int kq = (tid & 3) << 2;
            int t = toks[r];
            float4 v = make_float4(0.f, 0.f, 0.f, 0.f);
            if (t >= 0) v = *(const float4*)(g_xn + (size_t)t * Dd + k0 + kq);
            As[kq + 0][r] = v.x; As[kq + 1][r] = v.y;
            As[kq + 2][r] = v.z; As[kq + 3][r] = v.w;

            float4 w = *(const float4*)(W + (size_t)(bn + r) * Dd + k0 + kq);
            Ws[kq + 0][r] = w.x; Ws[kq + 1][r] = w.y;
            Ws[kq + 2][r] = w.z; Ws[kq + 3][r] = w.w;
        }
        __syncthreads();
        #pragma unroll
        for (int kk = 0; kk < 16; kk++) {
            float4 a0 = *(const float4*)&As[kk][ty * 4];
            float4 b0 = *(const float4*)&Ws[kk][tx * 4];
            float a[4] = {a0.x, a0.y, a0.z, a0.w};
            float b[4] = {b0.x, b0.y, b0.z, b0.w};
            #pragma unroll
            for (int i = 0; i < 4; i++)
                #pragma unroll
                for (int j = 0; j < 4; j++) acc[i][j] += a[i] * b[j];
        }
        __syncthreads();
    }
    #pragma unroll
    for (int i = 0; i < 4; i++) {
        int s = row0 + ty * 4 + i;
        if (s < cnt) {
            int t = toks[ty * 4 + i];
            float p = pb[ty * 4 + i];
            #pragma unroll
            for (int j = 0; j < 4; j++) {
                int c = bn + tx * 4 + j;
                g_x[(size_t)t * Dd + c] += p * (acc[i][j] + b_exp[e * Dd + c]);
            }
        }
    }
}

// ---------------- output ----------------------------------------------------
__global__ void k_out(float* __restrict__ out, int n) {
    int idx = blockIdx.x * 256 + threadIdx.x;
    if (idx < n) {
        if (idx < Tt * Dd) out[idx] = g_x[idx];
        else out[idx] = g_aux;
    }
}

// ---------------- launch -----------------------------------------------------
extern "C" void kernel_launch(void* const* d_in, const int* in_sizes, int n_in,
                              void* d_out, int out_size) {
    const int*   tokens = (const int*)d_in[0];
    const float* emb    = (const float*)d_in[1];
    const float* w_qkv  = (const float*)d_in[2];
    const float* b_qkv  = (const float*)d_in[3];
    const float* w_out  = (const float*)d_in[4];
    const float* b_out  = (const float*)d_in[5];
    const float* attn_g = (const float*)d_in[6];
    const float* attn_b = (const float*)d_in[7];
    const float* moe_g  = (const float*)d_in[8];
    const float* moe_b  = (const float*)d_in[9];
    const float* w_gate = (const float*)d_in[10];
    const float* w_exp  = (const float*)d_in[11];
    const float* b_exp  = (const float*)d_in[12];

    float *px, *pxn, *pqkv, *pattn;
    cudaGetSymbolAddress((void**)&px, g_x);
    cudaGetSymbolAddress((void**)&pxn, g_xn);
    cudaGetSymbolAddress((void**)&pqkv, g_qkv);
    cudaGetSymbolAddress((void**)&pattn, g_attn);

    k_init<<<1, 1>>>();
    k_embed<<<(Tt * Dd) / 256, 256>>>(tokens, emb);

    for (int l = 0; l < Ll; l++) {
        // attention block
        k_ln<<<Tt, 256>>>(attn_g + (size_t)l * Dd, attn_b + (size_t)l * Dd);
        k_gemm<<<dim3((3 * Dd) / 64, Tt / 128), 256>>>(pxn, w_qkv, b_qkv, nullptr, pqkv,
                                                        Tt, 3 * Dd, Dd);
        k_attn<<<dim3(Bb * Hh, Ss / 32), 256>>>();
        k_gemm<<<dim3(Dd / 64, Tt / 128), 256>>>(pattn, w_out, b_out, px, px,
                                                  Tt, Dd, Dd);
        // MoE block
        k_ln<<<Tt, 256>>>(moe_g + (size_t)l * Dd, moe_b + (size_t)l * Dd);
        k_zero16<<<1, 16>>>();
        k_gate<<<Tt / 8, 256>>>(w_gate);
        k_route<<<1, 256>>>();
        k_moe<<<dim3(Dd / 64, (CAPe + 63) / 64, NE), 256>>>(w_exp, b_exp);
    }

    k_out<<<(out_size + 255) / 256, 256>>>((float*)d_out, out_size);
}

// round 3
// speedup vs baseline: 1.1592x; 1.1592x over previous
#include <cuda_runtime.h>
#include <math.h>

#define Bb 2
#define Ss 1024
#define Tt 2048
#define Dd 2048
#define Ll 4
#define NE 16
#define Hh 16
#define DHh 128
#define CAPe 153

typedef unsigned long long u64;

// ---------------- packed f32x2 helpers (sm_103a) ----------------------------
__device__ __forceinline__ void ffma2(u64& d, u64 a, u64 b) {
    asm("fma.rn.f32x2 %0, %1, %2, %0;" : "+l"(d) : "l"(a), "l"(b));
}
__device__ __forceinline__ u64 fmul2(u64 a, u64 b) {
    u64 r; asm("mul.rn.f32x2 %0, %1, %2;" : "=l"(r) : "l"(a), "l"(b)); return r;
}
__device__ __forceinline__ u64 pk2(float x, float y) {
    u64 r; asm("mov.b64 %0, {%1, %2};" : "=l"(r) : "f"(x), "f"(y)); return r;
}
__device__ __forceinline__ void upk2(u64 v, float& x, float& y) {
    asm("mov.b64 {%0, %1}, %2;" : "=f"(x), "=f"(y) : "l"(v));
}

// ---------------- scratch (static device globals; no allocations) ----------
__device__ float g_x[Tt * Dd];
__device__ float g_xn[Tt * Dd];
__device__ float g_qkv[Tt * 3 * Dd];
__device__ float g_attn[Tt * Dd];
__device__ int   g_expert[Tt];
__device__ float g_prob[Tt];
__device__ float g_probsum[NE];
__device__ int   g_tok[NE * CAPe];
__device__ int   g_cnt[NE];
__device__ float g_aux;

__global__ void k_init() { g_aux = 0.0f; }
__global__ void k_zero16() { if (threadIdx.x < NE) g_probsum[threadIdx.x] = 0.0f; }

// ---------------- embedding gather ------------------------------------------
__global__ void k_embed(const int* __restrict__ tokens, const float* __restrict__ emb) {
    int idx = blockIdx.x * 256 + threadIdx.x;
    int t = idx / Dd;
    int d = idx % Dd;
    g_x[idx] = emb[(size_t)tokens[t] * Dd + d];
}

// ---------------- layernorm -------------------------------------------------
__global__ void k_ln(const float* __restrict__ gamma, const float* __restrict__ beta) {
    int t = blockIdx.x;
    const float* row = g_x + (size_t)t * Dd;
    float s = 0.f, s2 = 0.f;
    for (int d = threadIdx.x; d < Dd; d += 256) {
        float v = row[d];
        s += v; s2 += v * v;
    }
    #pragma unroll
    for (int o = 16; o; o >>= 1) {
        s  += __shfl_xor_sync(0xffffffffu, s, o);
        s2 += __shfl_xor_sync(0xffffffffu, s2, o);
    }
    __shared__ float shs[8], shs2[8];
    __shared__ float smu, srstd;
    int w = threadIdx.x >> 5, ln = threadIdx.x & 31;
    if (ln == 0) { shs[w] = s; shs2[w] = s2; }
    __syncthreads();
    if (threadIdx.x == 0) {
        float a = 0.f, b2 = 0.f;
        #pragma unroll
        for (int i = 0; i < 8; i++) { a += shs[i]; b2 += shs2[i]; }
        float m = a / (float)Dd;
        float var = b2 / (float)Dd - m * m;
        smu = m;
        srstd = rsqrtf(var + 1e-5f);
    }
    __syncthreads();
    float mu = smu, rstd = srstd;
    for (int d = threadIdx.x; d < Dd; d += 256)
        g_xn[(size_t)t * Dd + d] = (row[d] - mu) * rstd * gamma[d] + beta[d];
}

// ---------------- GEMM: C = A[MxK] * W[NxK]^T + bias (+res) -----------------
// BM=128, BN=128, BK=16, 256 threads, 8x8 per thread, packed f32x2 FMA,
// register-prefetch double buffering.
__global__ void __launch_bounds__(256, 2)
k_gemm(const float* __restrict__ A, const float* __restrict__ W,
       const float* __restrict__ bias, const float* __restrict__ res,
       float* __restrict__ C, int M, int N, int K) {
    __shared__ float As[16][132];
    __shared__ float Ws[16][132];
    int bm = blockIdx.y * 128, bn = blockIdx.x * 128;
    int tid = threadIdx.x;
    int ty = tid >> 4, tx = tid & 15;     // 16x16 thread grid; 8x8 each

    int rA = tid >> 2;                    // 0..63
    int kq = (tid & 3) << 2;              // 0,4,8,12

    u64 acc[8][4];
    #pragma unroll
    for (int i = 0; i < 8; i++)
        #pragma unroll
        for (int j = 0; j < 4; j++) acc[i][j] = 0ULL;

    const float* Ap0 = A + (size_t)(bm + rA) * K + kq;
    const float* Ap1 = A + (size_t)(bm + rA + 64) * K + kq;
    const float* Wp0 = W + (size_t)(bn + rA) * K + kq;
    const float* Wp1 = W + (size_t)(bn + rA + 64) * K + kq;

    float4 ra0 = *(const float4*)(Ap0);
    float4 ra1 = *(const float4*)(Ap1);
    float4 rw0 = *(const float4*)(Wp0);
    float4 rw1 = *(const float4*)(Wp1);

    for (int k0 = 0; k0 < K; k0 += 16) {
        As[kq + 0][rA] = ra0.x; As[kq + 1][rA] = ra0.y;
        As[kq + 2][rA] = ra0.z; As[kq + 3][rA] = ra0.w;
        As[kq + 0][rA + 64] = ra1.x; As[kq + 1][rA + 64] = ra1.y;
        As[kq + 2][rA + 64] = ra1.z; As[kq + 3][rA + 64] = ra1.w;
        Ws[kq + 0][rA] = rw0.x; Ws[kq + 1][rA] = rw0.y;
        Ws[kq + 2][rA] = rw0.z; Ws[kq + 3][rA] = rw0.w;
        Ws[kq + 0][rA + 64] = rw1.x; Ws[kq + 1][rA + 64] = rw1.y;
        Ws[kq + 2][rA + 64] = rw1.z; Ws[kq + 3][rA + 64] = rw1.w;
        __syncthreads();

        if (k0 + 16 < K) {
            ra0 = *(const float4*)(Ap0 + k0 + 16);
            ra1 = *(const float4*)(Ap1 + k0 + 16);
            rw0 = *(const float4*)(Wp0 + k0 + 16);
            rw1 = *(const float4*)(Wp1 + k0 + 16);
        }

        #pragma unroll
        for (int kk = 0; kk < 16; kk++) {
            float4 a0 = *(const float4*)&As[kk][ty * 8];
            float4 a1 = *(const float4*)&As[kk][ty * 8 + 4];
            ulonglong2 w0 = *(const ulonglong2*)&Ws[kk][tx * 8];
            ulonglong2 w1 = *(const ulonglong2*)&Ws[kk][tx * 8 + 4];
            u64 b[4] = {w0.x, w0.y, w1.x, w1.y};
            float av[8] = {a0.x, a0.y, a0.z, a0.w, a1.x, a1.y, a1.z, a1.w};
            #pragma unroll
            for (int i = 0; i < 8; i++) {
                u64 ad = pk2(av[i], av[i]);
                #pragma unroll
                for (int j = 0; j < 4; j++) ffma2(acc[i][j], ad, b[j]);
            }
        }
        __syncthreads();
    }

    int c0 = bn + tx * 8;
    float4 bi0 = *(const float4*)(bias + c0);
    float4 bi1 = *(const float4*)(bias + c0 + 4);
    float bv[8] = {bi0.x, bi0.y, bi0.z, bi0.w, bi1.x, bi1.y, bi1.z, bi1.w};
    #pragma unroll
    for (int i = 0; i < 8; i++) {
        int r = bm + ty * 8 + i;
        float o[8];
        #pragma unroll
        for (int j = 0; j < 4; j++) upk2(acc[i][j], o[2 * j], o[2 * j + 1]);
        #pragma unroll
        for (int j = 0; j < 8; j++) o[j] += bv[j];
        if (res) {
            float4 r0 = *(const float4*)(res + (size_t)r * N + c0);
            float4 r1 = *(const float4*)(res + (size_t)r * N + c0 + 4);
            o[0] += r0.x; o[1] += r0.y; o[2] += r0.z; o[3] += r0.w;
            o[4] += r1.x; o[5] += r1.y; o[6] += r1.z; o[7] += r1.w;
        }
        *(float4*)(C + (size_t)r * N + c0)     = make_float4(o[0], o[1], o[2], o[3]);
        *(float4*)(C + (size_t)r * N + c0 + 4) = make_float4(o[4], o[5], o[6], o[7]);
    }
}

// ---------------- attention (flash-style, BQ=32, BKV=32, packed fma) --------
__global__ void __launch_bounds__(256, 2) k_attn() {
    int bh = blockIdx.x;
    int b = bh >> 4, h = bh & 15;
    int q0 = blockIdx.y * 32;
    __shared__ float Qs[32][132];
    __shared__ float KVs[32][132];   // K then V (reused buffer)
    __shared__ float Sc[32][36];
    int tid = threadIdx.x;

    // load Q tile
    #pragma unroll
    for (int j = 0; j < 4; j++) {
        int i = tid + j * 256;                 // 1024 float4
        int r = i >> 5, d4 = (i & 31) << 2;
        float4 v = *(const float4*)&g_qkv[(size_t)(b * Ss + q0 + r) * (3 * Dd) + h * DHh + d4];
        *(float4*)&Qs[r][d4] = v;
    }

    int q  = tid >> 3;       // 0..31
    int dp = tid & 7;        // 8 d-slices of 16
    float m = -1e30f, l = 0.f;
    u64 acc2[8];
    #pragma unroll
    for (int j = 0; j < 8; j++) acc2[j] = 0ULL;

    const float scale = 0.08838834764831845f;  // 1/sqrt(128)

    for (int kb = 0; kb < Ss; kb += 32) {
        __syncthreads();
        // load K tile
        #pragma unroll
        for (int j = 0; j < 4; j++) {
            int i = tid + j * 256;
            int r = i >> 5, d4 = (i & 31) << 2;
            float4 v = *(const float4*)&g_qkv[(size_t)(b * Ss + kb + r) * (3 * Dd) + Dd + h * DHh + d4];
            *(float4*)&KVs[r][d4] = v;
        }
        __syncthreads();

        // scores: 4 per thread, swizzled k = dp + 8*kk (bank-conflict free)
        // FULL 128-dim dot product: 4 packed pairs per 16-float chunk.
        {
            u64 s2[4] = {0ULL, 0ULL, 0ULL, 0ULL};
            #pragma unroll
            for (int ch = 0; ch < 8; ch++) {
                ulonglong2 qa = *(const ulonglong2*)&Qs[q][ch * 16];       // d 0..3
                ulonglong2 qb = *(const ulonglong2*)&Qs[q][ch * 16 + 4];   // d 4..7
                ulonglong2 qc = *(const ulonglong2*)&Qs[q][ch * 16 + 8];   // d 8..11
                ulonglong2 qd = *(const ulonglong2*)&Qs[q][ch * 16 + 12];  // d 12..15
                #pragma unroll
                for (int kk = 0; kk < 4; kk++) {
                    int k = dp + kk * 8;
                    ulonglong2 ka = *(const ulonglong2*)&KVs[k][ch * 16];
                    ulonglong2 kb2 = *(const ulonglong2*)&KVs[k][ch * 16 + 4];
                    ulonglong2 kc = *(const ulonglong2*)&KVs[k][ch * 16 + 8];
                    ulonglong2 kd = *(const ulonglong2*)&KVs[k][ch * 16 + 12];
                    ffma2(s2[kk], qa.x, ka.x);
                    ffma2(s2[kk], qa.y, ka.y);
                    ffma2(s2[kk], qb.x, kb2.x);
                    ffma2(s2[kk], qb.y, kb2.y);
                    ffma2(s2[kk], qc.x, kc.x);
                    ffma2(s2[kk], qc.y, kc.y);
                    ffma2(s2[kk], qd.x, kd.x);
                    ffma2(s2[kk], qd.y, kd.y);
                }
            }
            #pragma unroll
            for (int kk = 0; kk < 4; kk++) {
                float lo, hi; upk2(s2[kk], lo, hi);
                Sc[q][dp + kk * 8] = (lo + hi) * scale;
            }
        }
        __syncthreads();

        // load V tile into same buffer
        #pragma unroll
        for (int j = 0; j < 4; j++) {
            int i = tid + j * 256;
            int r = i >> 5, d4 = (i & 31) << 2;
            float4 v = *(const float4*)&g_qkv[(size_t)(b * Ss + kb + r) * (3 * Dd) + 2 * Dd + h * DHh + d4];
            *(float4*)&KVs[r][d4] = v;
        }

        // softmax bookkeeping (uses Sc only)
        float sc[32];
        #pragma unroll
        for (int k = 0; k < 32; k++) sc[k] = Sc[q][k];
        float mx = -1e30f;
        #pragma unroll
        for (int k = 0; k < 32; k++) mx = fmaxf(mx, sc[k]);
        float nm = fmaxf(m, mx);
        float corr = __expf(m - nm);
        l *= corr;
        u64 cp = pk2(corr, corr);
        #pragma unroll
        for (int j = 0; j < 8; j++) acc2[j] = fmul2(acc2[j], cp);
        float p[32];
        #pragma unroll
        for (int k = 0; k < 32; k++) { p[k] = __expf(sc[k] - nm); l += p[k]; }
        m = nm;

        __syncthreads();   // V ready
        #pragma unroll
        for (int k = 0; k < 32; k++) {
            u64 pp = pk2(p[k], p[k]);
            ulonglong2 v0 = *(const ulonglong2*)&KVs[k][dp * 16];       // f 0..3
            ulonglong2 v1 = *(const ulonglong2*)&KVs[k][dp * 16 + 4];   // f 4..7
            ulonglong2 v2 = *(const ulonglong2*)&KVs[k][dp * 16 + 8];   // f 8..11
            ulonglong2 v3 = *(const ulonglong2*)&KVs[k][dp * 16 + 12];  // f 12..15
            ffma2(acc2[0], pp, v0.x);
            ffma2(acc2[1], pp, v0.y);
            ffma2(acc2[2], pp, v1.x);
            ffma2(acc2[3], pp, v1.y);
            ffma2(acc2[4], pp, v2.x);
            ffma2(acc2[5], pp, v2.y);
            ffma2(acc2[6], pp, v3.x);
            ffma2(acc2[7], pp, v3.y);
        }
    }
    float inv = 1.f / l;
    int t = b * Ss + q0 + q;
    float* op = g_attn + (size_t)t * Dd + h * DHh + dp * 16;
    float o[16];
    upk2(acc2[0], o[0],  o[1]);   upk2(acc2[1], o[2],  o[3]);
    upk2(acc2[2], o[4],  o[5]);   upk2(acc2[3], o[6],  o[7]);
    upk2(acc2[4], o[8],  o[9]);   upk2(acc2[5], o[10], o[11]);
    upk2(acc2[6], o[12], o[13]);  upk2(acc2[7], o[14], o[15]);
    #pragma unroll
    for (int j = 0; j < 16; j++) op[j] = o[j] * inv;
}

// ---------------- gate ------------------------------------------------------
__global__ void k_gate(const float* __restrict__ wg) {
    int warp = threadIdx.x >> 5;
    int lane = threadIdx.x & 31;
    int t = blockIdx.x * 8 + warp;
    __shared__ float bsum[NE];
    if (threadIdx.x < NE) bsum[threadIdx.x] = 0.f;
    __syncthreads();

    float lg[16];
    #pragma unroll
    for (int e = 0; e < 16; e++) lg[e] = 0.f;
    const float* row = g_xn + (size_t)t * Dd;
    for (int d = lane; d < Dd; d += 32) {
        float x = row[d];
        const float* w = wg + (size_t)d * NE;
        #pragma unroll
        for (int e = 0; e < 16; e++) lg[e] += x * w[e];
    }
    #pragma unroll
    for (int e = 0; e < 16; e++)
        #pragma unroll
        for (int o = 16; o; o >>= 1) lg[e] += __shfl_xor_sync(0xffffffffu, lg[e], o);

    float mx = lg[0];
    #pragma unroll
    for (int e = 1; e < 16; e++) mx = fmaxf(mx, lg[e]);
    float pe[16]; float se = 0.f;
    #pragma unroll
    for (int e = 0; e < 16; e++) { pe[e] = __expf(lg[e] - mx); se += pe[e]; }
    float inv = 1.f / se;

    if (lane == 0) {
        int be = 0; float bl = lg[0];
        #pragma unroll
        for (int e = 1; e < 16; e++) if (lg[e] > bl) { bl = lg[e]; be = e; }
        g_expert[t] = be;
        g_prob[t] = pe[be] * inv;
        #pragma unroll
        for (int e = 0; e < 16; e++) atomicAdd(&bsum[e], pe[e] * inv);
    }
    __syncthreads();
    if (threadIdx.x < NE) atomicAdd(&g_probsum[threadIdx.x], bsum[threadIdx.x]);
}

// ---------------- routing ---------------------------------------------------
__global__ void k_route() {
    __shared__ int sh_e[Tt];
    __shared__ int cnts[256][NE];
    __shared__ int tot[NE];
    int tid = threadIdx.x;
    for (int i = tid; i < Tt; i += 256) sh_e[i] = g_expert[i];
    #pragma unroll
    for (int e = 0; e < NE; e++) cnts[tid][e] = 0;
    __syncthreads();
    for (int i = 0; i < 8; i++) {
        int e = sh_e[tid * 8 + i];
        cnts[tid][e]++;
    }
    __syncthreads();
    if (tid < NE) {
        int run = 0;
        for (int i = 0; i < 256; i++) {
            int c = cnts[i][tid];
            cnts[i][tid] = run;
            run += c;
        }
        tot[tid] = run;
        g_cnt[tid] = (run < CAPe) ? run : CAPe;
    }
    __syncthreads();
    for (int i = 0; i < 8; i++) {
        int t = tid * 8 + i;
        int e = sh_e[t];
        int r = cnts[tid][e]++;
        if (r < CAPe) g_tok[e * CAPe + r] = t;
    }
    if (tid == 0) {
        float a = 0.f;
        for (int e = 0; e < NE; e++) a += (float)tot[e] * g_probsum[e];
        g_aux += a * ((float)NE / ((float)Tt * (float)Tt));
    }
}

// ---------------- MoE expert GEMM, x += p*(h@W^T+b) -------------------------
// BM=64, BN=128, BK=16, 256 threads, 4x8 per thread, packed fma
__global__ void __launch_bounds__(256, 2)
k_moe(const float* __restrict__ w_exp, const float* __restrict__ b_exp) {
    int e = blockIdx.z;
    int cnt = g_cnt[e];
    int row0 = blockIdx.y * 64;
    if (row0 >= cnt) return;
    int bn = blockIdx.x * 128;
    int tid = threadIdx.x;

    __shared__ int   toks[64];
    __shared__ float pb[64];
    __shared__ float As[16][68];
    __shared__ float Ws[16][132];

    if (tid < 64) {
        int s = row0 + tid;
        if (s < cnt) {
            int t = g_tok[e * CAPe + s];
            toks[tid] = t;
            pb[tid] = g_prob[t];
        } else {
            toks[tid] = -1;
            pb[tid] = 0.f;
        }
    }
    __syncthreads();

    int ty = tid >> 4, tx = tid & 15;    // rows ty*4.., cols tx*8..
    u64 acc[4][4];
    #pragma unroll
    for (int i = 0; i < 4; i++)
        #pragma unroll
        for (int j = 0; j < 4; j++) acc[i][j] = 0ULL;

    const float* W = w_exp + (size_t)e * Dd * Dd;
    int rA = tid >> 2;                   // 0..63
    int kq = (tid & 3) << 2;
    int tA = toks[rA];
    const float* Ap = (tA >= 0) ? (g_xn + (size_t)tA * Dd + kq) : nullptr;
    const float* Wp0 = W + (size_t)(bn + rA) * Dd + kq;
    const float* Wp1 = W + (size_t)(bn + rA + 64) * Dd + kq;

    float4 ra = Ap ? *(const float4*)(Ap) : make_float4(0.f, 0.f, 0.f, 0.f);
    float4 rw0 = *(const float4*)(Wp0);
    float4 rw1 = *(const float4*)(Wp1);

    for (int k0 = 0; k0 < Dd; k0 += 16) {
        As[kq + 0][rA] = ra.x; As[kq + 1][rA] = ra.y;
        As[kq + 2][rA] = ra.z; As[kq + 3][rA] = ra.w;
        Ws[kq + 0][rA] = rw0.x; Ws[kq + 1][rA] = rw0.y;
        Ws[kq + 2][rA] = rw0.z; Ws[kq + 3][rA] = rw0.w;
        Ws[kq + 0][rA + 64] = rw1.x; Ws[kq + 1][rA + 64] = rw1.y;
        Ws[kq + 2][rA + 64] = rw1.z; Ws[kq + 3][rA + 64] = rw1.w;
        __syncthreads();

        if (k0 + 16 < Dd) {
            ra = Ap ? *(const float4*)(Ap + k0 + 16) : make_float4(0.f, 0.f, 0.f, 0.f);
            rw0 = *(const float4*)(Wp0 + k0 + 16);
            rw1 = *(const float4*)(Wp1 + k0 + 16);
        }

        #pragma unroll
        for (int kk = 0; kk < 16; kk++) {
            float4 a0 = *(const float4*)&As[kk][ty * 4];
            ulonglong2 w0 = *(const ulonglong2*)&Ws[kk][tx * 8];
            ulonglong2 w1 = *(const ulonglong2*)&Ws[kk][tx * 8 + 4];
            u64 b[4] = {w0.x, w0.y, w1.x, w1.y};
            float av[4] = {a0.x, a0.y, a0.z, a0.w};
            #pragma unroll
            for (int i = 0; i < 4; i++) {
                u64 ad = pk2(av[i], av[i]);
                #pragma unroll
                for (int j = 0; j < 4; j++) ffma2(acc[i][j], ad, b[j]);
            }
        }
        __syncthreads();
    }

    int c0 = bn + tx * 8;
    float4 be0 = *(const float4*)(b_exp + e * Dd + c0);
    float4 be1 = *(const float4*)(b_exp + e * Dd + c0 + 4);
    float bv[8] = {be0.x, be0.y, be0.z, be0.w, be1.x, be1.y, be1.z, be1.w};
    #pragma unroll
    for (int i = 0; i < 4; i++) {
        int s = row0 + ty * 4 + i;
        if (s < cnt) {
            int t = toks[ty * 4 + i];
            float p = pb[ty * 4 + i];
            float o[8];
            #pragma unroll
            for (int j = 0; j < 4; j++) upk2(acc[i][j], o[2 * j], o[2 * j + 1]);
            float* xp = g_x + (size_t)t * Dd + c0;
            #pragma unroll
            for (int j = 0; j < 8; j++) xp[j] += p * (o[j] + bv[j]);
        }
    }
}

// ---------------- output ----------------------------------------------------
__global__ void k_out(float* __restrict__ out, int n) {
    int idx = blockIdx.x * 256 + threadIdx.x;
    if (idx < n) {
        if (idx < Tt * Dd) out[idx] = g_x[idx];
        else out[idx] = g_aux;
    }
}

// ---------------- launch ----------------------------------------------------
extern "C" void kernel_launch(void* const* d_in, const int* in_sizes, int n_in,
                              void* d_out, int out_size) {
    const int*   tokens = (const int*)d_in[0];
    const float* emb    = (const float*)d_in[1];
    const float* w_qkv  = (const float*)d_in[2];
    const float* b_qkv  = (const float*)d_in[3];
    const float* w_out  = (const float*)d_in[4];
    const float* b_out  = (const float*)d_in[5];
    const float* attn_g = (const float*)d_in[6];
    const float* attn_b = (const float*)d_in[7];
    const float* moe_g  = (const float*)d_in[8];
    const float* moe_b  = (const float*)d_in[9];
    const float* w_gate = (const float*)d_in[10];
    const float* w_exp  = (const float*)d_in[11];
    const float* b_exp  = (const float*)d_in[12];

    float *px, *pxn, *pqkv, *pattn;
    cudaGetSymbolAddress((void**)&px, g_x);
    cudaGetSymbolAddress((void**)&pxn, g_xn);
    cudaGetSymbolAddress((void**)&pqkv, g_qkv);
    cudaGetSymbolAddress((void**)&pattn, g_attn);

    k_init<<<1, 1>>>();
    k_embed<<<(Tt * Dd) / 256, 256>>>(tokens, emb);

    for (int l = 0; l < Ll; l++) {
        k_ln<<<Tt, 256>>>(attn_g + (size_t)l * Dd, attn_b + (size_t)l * Dd);
        k_gemm<<<dim3((3 * Dd) / 128, Tt / 128), 256>>>(pxn, w_qkv, b_qkv, nullptr, pqkv,
                                                        Tt, 3 * Dd, Dd);
        k_attn<<<dim3(Bb * Hh, Ss / 32), 256>>>();
        k_gemm<<<dim3(Dd / 128, Tt / 128), 256>>>(pattn, w_out, b_out, px, px,
                                                  Tt, Dd, Dd);
        k_ln<<<Tt, 256>>>(moe_g + (size_t)l * Dd, moe_b + (size_t)l * Dd);
        k_zero16<<<1, 16>>>();
        k_gate<<<Tt / 8, 256>>>(w_gate);
        k_route<<<1, 256>>>();
        k_moe<<<dim3(Dd / 128, (CAPe + 63) / 64, NE), 256>>>(w_exp, b_exp);
    }

    k_out<<<(out_size + 255) / 256, 256>>>((float*)d_out, out_size);
}

// round 5
// speedup vs baseline: 1.3265x; 1.1443x over previous
#include <cuda_runtime.h>
#include <math.h>
#include <stdint.h>

#define Bb 2
#define Ss 1024
#define Tt 2048
#define Dd 2048
#define Ll 4
#define NE 16
#define Hh 16
#define DHh 128
#define CAPe 153

typedef unsigned long long u64;

// ---------------- packed f32x2 helpers (sm_103a) ----------------------------
__device__ __forceinline__ void ffma2(u64& d, u64 a, u64 b) {
    asm("fma.rn.f32x2 %0, %1, %2, %0;" : "+l"(d) : "l"(a), "l"(b));
}
__device__ __forceinline__ u64 fmul2(u64 a, u64 b) {
    u64 r; asm("mul.rn.f32x2 %0, %1, %2;" : "=l"(r) : "l"(a), "l"(b)); return r;
}
__device__ __forceinline__ u64 pk2(float x, float y) {
    u64 r; asm("mov.b64 %0, {%1, %2};" : "=l"(r) : "f"(x), "f"(y)); return r;
}
__device__ __forceinline__ void upk2(u64 v, float& x, float& y) {
    asm("mov.b64 {%0, %1}, %2;" : "=f"(x), "=f"(y) : "l"(v));
}

// ---------------- tf32 helpers ----------------------------------------------
__device__ __forceinline__ float tf32r(float x) {
    uint32_t u; asm("cvt.rna.tf32.f32 %0, %1;" : "=r"(u) : "f"(x));
    return __uint_as_float(u);
}
// D += A * B  (m16n8k8, tf32 inputs, f32 accum)
__device__ __forceinline__ void mma8(float* d, const uint32_t* a, const uint32_t* b) {
    asm volatile(
        "mma.sync.aligned.m16n8k8.row.col.f32.tf32.tf32.f32 "
        "{%0,%1,%2,%3}, {%4,%5,%6,%7}, {%8,%9}, {%0,%1,%2,%3};"
        : "+f"(d[0]), "+f"(d[1]), "+f"(d[2]), "+f"(d[3])
        : "r"(a[0]), "r"(a[1]), "r"(a[2]), "r"(a[3]), "r"(b[0]), "r"(b[1]));
}

// smem float offsets (stride 36 per row; 36 == 4 mod 32 -> conflict free)
#define AS_HI 0
#define AS_LO 4608
#define WS_HI 9216
#define WS_LO 11520
#define MMA_SMEM_FLOATS 13824
#define MMA_SMEM_BYTES  (MMA_SMEM_FLOATS * 4)

// ---------------- scratch (static device globals; no allocations) ----------
__device__ float g_x[Tt * Dd];
__device__ float g_xn[Tt * Dd];
__device__ float g_qkv[Tt * 3 * Dd];
__device__ float g_attn[Tt * Dd];
__device__ int   g_expert[Tt];
__device__ float g_prob[Tt];
__device__ float g_probsum[NE];
__device__ int   g_tok[NE * CAPe];
__device__ int   g_cnt[NE];
__device__ float g_aux;

__global__ void k_init() { g_aux = 0.0f; }
__global__ void k_zero16() { if (threadIdx.x < NE) g_probsum[threadIdx.x] = 0.0f; }

// ---------------- embedding gather ------------------------------------------
__global__ void k_embed(const int* __restrict__ tokens, const float* __restrict__ emb) {
    int idx = blockIdx.x * 256 + threadIdx.x;
    int t = idx / Dd;
    int d = idx % Dd;
    g_x[idx] = emb[(size_t)tokens[t] * Dd + d];
}

// ---------------- layernorm -------------------------------------------------
__global__ void k_ln(const float* __restrict__ gamma, const float* __restrict__ beta) {
    int t = blockIdx.x;
    const float* row = g_x + (size_t)t * Dd;
    float s = 0.f, s2 = 0.f;
    for (int d = threadIdx.x; d < Dd; d += 256) {
        float v = row[d];
        s += v; s2 += v * v;
    }
    #pragma unroll
    for (int o = 16; o; o >>= 1) {
        s  += __shfl_xor_sync(0xffffffffu, s, o);
        s2 += __shfl_xor_sync(0xffffffffu, s2, o);
    }
    __shared__ float shs[8], shs2[8];
    __shared__ float smu, srstd;
    int w = threadIdx.x >> 5, ln = threadIdx.x & 31;
    if (ln == 0) { shs[w] = s; shs2[w] = s2; }
    __syncthreads();
    if (threadIdx.x == 0) {
        float a = 0.f, b2 = 0.f;
        #pragma unroll
        for (int i = 0; i < 8; i++) { a += shs[i]; b2 += shs2[i]; }
        float m = a / (float)Dd;
        float var = b2 / (float)Dd - m * m;
        smu = m;
        srstd = rsqrtf(var + 1e-5f);
    }
    __syncthreads();
    float mu = smu, rstd = srstd;
    for (int d = threadIdx.x; d < Dd; d += 256)
        g_xn[(size_t)t * Dd + d] = (row[d] - mu) * rstd * gamma[d] + beta[d];
}

// ---------------- helpers for mma GEMM staging -------------------------------
__device__ __forceinline__ void split_store(float* sm, int hi_off, int lo_off,
                                            int pos, float4 v) {
    float4 h, l;
    h.x = tf32r(v.x); l.x = tf32r(v.x - h.x);
    h.y = tf32r(v.y); l.y = tf32r(v.y - h.y);
    h.z = tf32r(v.z); l.z = tf32r(v.z - h.z);
    h.w = tf32r(v.w); l.w = tf32r(v.w - h.w);
    *(float4*)(sm + hi_off + pos) = h;
    *(float4*)(sm + lo_off + pos) = l;
}

// inner compute: one BK=32 chunk, warp computes 32x32 via m16n8k8 x (2x4) x3
__device__ __forceinline__ void mma_chunk(const float* sm, int wr, int wc,
                                          int grp, int qid, float acc[2][4][4]) {
    #pragma unroll
    for (int ks = 0; ks < 4; ks++) {
        int kc = ks * 8;
        uint32_t ahi[2][4], alo[2][4], bhi[4][2], blo[4][2];
        #pragma unroll
        for (int mi = 0; mi < 2; mi++) {
            int rb = wr * 32 + mi * 16;
            int i00 = (rb + grp) * 36 + kc + qid;
            int i10 = (rb + grp + 8) * 36 + kc + qid;
            ahi[mi][0] = *(const uint32_t*)(sm + AS_HI + i00);
            ahi[mi][1] = *(const uint32_t*)(sm + AS_HI + i10);
            ahi[mi][2] = *(const uint32_t*)(sm + AS_HI + i00 + 4);
            ahi[mi][3] = *(const uint32_t*)(sm + AS_HI + i10 + 4);
            alo[mi][0] = *(const uint32_t*)(sm + AS_LO + i00);
            alo[mi][1] = *(const uint32_t*)(sm + AS_LO + i10);
            alo[mi][2] = *(const uint32_t*)(sm + AS_LO + i00 + 4);
            alo[mi][3] = *(const uint32_t*)(sm + AS_LO + i10 + 4);
        }
        #pragma unroll
        for (int ni = 0; ni < 4; ni++) {
            int nb = wc * 32 + ni * 8;
            int i0 = (nb + grp) * 36 + kc + qid;
            bhi[ni][0] = *(const uint32_t*)(sm + WS_HI + i0);
            bhi[ni][1] = *(const uint32_t*)(sm + WS_HI + i0 + 4);
            blo[ni][0] = *(const uint32_t*)(sm + WS_LO + i0);
            blo[ni][1] = *(const uint32_t*)(sm + WS_LO + i0 + 4);
        }
        #pragma unroll
        for (int mi = 0; mi < 2; mi++)
            #pragma unroll
            for (int ni = 0; ni < 4; ni++) {
                mma8(acc[mi][ni], ahi[mi], bhi[ni]);
                mma8(acc[mi][ni], ahi[mi], blo[ni]);
                mma8(acc[mi][ni], alo[mi], bhi[ni]);
            }
    }
}

// ---------------- dense GEMM: C[M,N] = A[M,K] @ W[N,K]^T + bias (+res) ------
// BM=128, BN=64, BK=32, 256 threads (8 warps 4x2), tf32 3x split mma.sync
__global__ void __launch_bounds__(256, 2)
k_gemm_mma(const float* __restrict__ A, const float* __restrict__ W,
           const float* __restrict__ bias, const float* __restrict__ res,
           float* __restrict__ C, int N, int K) {
    extern __shared__ float sm[];
    int tid = threadIdx.x, wid = tid >> 5, lane = tid & 31;
    int grp = lane >> 2, qid = lane & 3;
    int wr = wid & 3, wc = wid >> 2;
    int bm = blockIdx.y * 128, bn = blockIdx.x * 64;

    float acc[2][4][4];
    #pragma unroll
    for (int mi = 0; mi < 2; mi++)
        #pragma unroll
        for (int ni = 0; ni < 4; ni++)
            #pragma unroll
            for (int j = 0; j < 4; j++) acc[mi][ni][j] = 0.f;

    // staging coords
    int rA[4], cA[4], posA[4];
    #pragma unroll
    for (int j = 0; j < 4; j++) {
        int idx = tid + j * 256;
        rA[j] = idx >> 3; cA[j] = (idx & 7) * 4;
        posA[j] = rA[j] * 36 + cA[j];
    }
    int rW[2], cW[2], posW[2];
    #pragma unroll
    for (int j = 0; j < 2; j++) {
        int idx = tid + j * 256;
        rW[j] = idx >> 3; cW[j] = (idx & 7) * 4;
        posW[j] = rW[j] * 36 + cW[j];
    }

    const float* Ab = A + (size_t)bm * K;
    const float* Wb = W + (size_t)bn * K;
    int nch = K / 32;

    float4 ra[4], rw[2];
    #pragma unroll
    for (int j = 0; j < 4; j++) ra[j] = *(const float4*)(Ab + (size_t)rA[j] * K + cA[j]);
    #pragma unroll
    for (int j = 0; j < 2; j++) rw[j] = *(const float4*)(Wb + (size_t)rW[j] * K + cW[j]);

    for (int c = 0; c < nch; c++) {
        #pragma unroll
        for (int j = 0; j < 4; j++) split_store(sm, AS_HI, AS_LO, posA[j], ra[j]);
        #pragma unroll
        for (int j = 0; j < 2; j++) split_store(sm, WS_HI, WS_LO, posW[j], rw[j]);
        __syncthreads();
        if (c + 1 < nch) {
            int k0 = (c + 1) * 32;
            #pragma unroll
            for (int j = 0; j < 4; j++) ra[j] = *(const float4*)(Ab + (size_t)rA[j] * K + k0 + cA[j]);
            #pragma unroll
            for (int j = 0; j < 2; j++) rw[j] = *(const float4*)(Wb + (size_t)rW[j] * K + k0 + cW[j]);
        }
        mma_chunk(sm, wr, wc, grp, qid, acc);
        __syncthreads();
    }

    // epilogue
    #pragma unroll
    for (int mi = 0; mi < 2; mi++) {
        #pragma unroll
        for (int ni = 0; ni < 4; ni++) {
            int r0 = bm + wr * 32 + mi * 16 + grp;
            int r1 = r0 + 8;
            int cc = bn + wc * 32 + ni * 8 + qid * 2;
            float b0 = bias[cc], b1 = bias[cc + 1];
            float v0 = acc[mi][ni][0] + b0, v1 = acc[mi][ni][1] + b1;
            float v2 = acc[mi][ni][2] + b0, v3 = acc[mi][ni][3] + b1;
            if (res) {
                v0 += res[(size_t)r0 * N + cc];
                v1 += res[(size_t)r0 * N + cc + 1];
                v2 += res[(size_t)r1 * N + cc];
                v3 += res[(size_t)r1 * N + cc + 1];
            }
            C[(size_t)r0 * N + cc]     = v0;
            C[(size_t)r0 * N + cc + 1] = v1;
            C[(size_t)r1 * N + cc]     = v2;
            C[(size_t)r1 * N + cc + 1] = v3;
        }
    }
}

// ---------------- MoE GEMM (mma): x[t] += p*(h[t] @ We^T + be) --------------
__global__ void __launch_bounds__(256, 2)
k_moe_mma(const float* __restrict__ w_exp, const float* __restrict__ b_exp) {
    int e = blockIdx.z;
    int cnt = g_cnt[e];
    int row0 = blockIdx.y * 128;
    if (row0 >= cnt) return;
    int bn = blockIdx.x * 64;

    extern __shared__ float sm[];
    __shared__ int   toks[128];
    __shared__ float pb[128];
    int tid = threadIdx.x, wid = tid >> 5, lane = tid & 31;
    int grp = lane >> 2, qid = lane & 3;
    int wr = wid & 3, wc = wid >> 2;

    if (tid < 128) {
        int s = row0 + tid;
        if (s < cnt) {
            int t = g_tok[e * CAPe + s];
            toks[tid] = t;
            pb[tid] = g_prob[t];
        } else {
            toks[tid] = -1;
            pb[tid] = 0.f;
        }
    }
    __syncthreads();

    float acc[2][4][4];
    #pragma unroll
    for (int mi = 0; mi < 2; mi++)
        #pragma unroll
        for (int ni = 0; ni < 4; ni++)
            #pragma unroll
            for (int j = 0; j < 4; j++) acc[mi][ni][j] = 0.f;

    int rA[4], cA[4], posA[4], tA[4];
    #pragma unroll
    for (int j = 0; j < 4; j++) {
        int idx = tid + j * 256;
        rA[j] = idx >> 3; cA[j] = (idx & 7) * 4;
        posA[j] = rA[j] * 36 + cA[j];
        tA[j] = toks[rA[j]];
    }
    int rW[2], cW[2], posW[2];
    #pragma unroll
    for (int j = 0; j < 2; j++) {
        int idx = tid + j * 256;
        rW[j] = idx >> 3; cW[j] = (idx & 7) * 4;
        posW[j] = rW[j] * 36 + cW[j];
    }

    const float* Wb = w_exp + (size_t)e * Dd * Dd + (size_t)bn * Dd;
    const int nch = Dd / 32;

    float4 ra[4], rw[2];
    #pragma unroll
    for (int j = 0; j < 4; j++)
        ra[j] = (tA[j] >= 0) ? *(const float4*)(g_xn + (size_t)tA[j] * Dd + cA[j])
                             : make_float4(0.f, 0.f, 0.f, 0.f);
    #pragma unroll
    for (int j = 0; j < 2; j++) rw[j] = *(const float4*)(Wb + (size_t)rW[j] * Dd + cW[j]);

    for (int c = 0; c < nch; c++) {
        #pragma unroll
        for (int j = 0; j < 4; j++) split_store(sm, AS_HI, AS_LO, posA[j], ra[j]);
        #pragma unroll
        for (int j = 0; j < 2; j++) split_store(sm, WS_HI, WS_LO, posW[j], rw[j]);
        __syncthreads();
        if (c + 1 < nch) {
            int k0 = (c + 1) * 32;
            #pragma unroll
            for (int j = 0; j < 4; j++)
                ra[j] = (tA[j] >= 0) ? *(const float4*)(g_xn + (size_t)tA[j] * Dd + k0 + cA[j])
                                     : make_float4(0.f, 0.f, 0.f, 0.f);
            #pragma unroll
            for (int j = 0; j < 2; j++) rw[j] = *(const float4*)(Wb + (size_t)rW[j] * Dd + k0 + cW[j]);
        }
        mma_chunk(sm, wr, wc, grp, qid, acc);
        __syncthreads();
    }

    const float* be = b_exp + (size_t)e * Dd;
    #pragma unroll
    for (int mi = 0; mi < 2; mi++) {
        int lr0 = wr * 32 + mi * 16 + grp;
        int lr1 = lr0 + 8;
        int s0 = row0 + lr0, s1 = row0 + lr1;
        #pragma unroll
        for (int ni = 0; ni < 4; ni++) {
            int cc = bn + wc * 32 + ni * 8 + qid * 2;
            float b0 = be[cc], b1 = be[cc + 1];
            if (s0 < cnt) {
                int t = toks[lr0]; float p = pb[lr0];
                g_x[(size_t)t * Dd + cc]     += p * (acc[mi][ni][0] + b0);
                g_x[(size_t)t * Dd + cc + 1] += p * (acc[mi][ni][1] + b1);
            }
            if (s1 < cnt) {
                int t = toks[lr1]; float p = pb[lr1];
                g_x[(size_t)t * Dd + cc]     += p * (acc[mi][ni][2] + b0);
                g_x[(size_t)t * Dd + cc + 1] += p * (acc[mi][ni][3] + b1);
            }
        }
    }
}

// ---------------- attention (flash-style, BQ=32, BKV=32, packed fma) --------
__global__ void __launch_bounds__(256, 2) k_attn() {
    int bh = blockIdx.x;
    int b = bh >> 4, h = bh & 15;
    int q0 = blockIdx.y * 32;
    __shared__ float Qs[32][132];
    __shared__ float KVs[32][132];
    __shared__ float Sc[32][36];
    int tid = threadIdx.x;

    #pragma unroll
    for (int j = 0; j < 4; j++) {
        int i = tid + j * 256;
        int r = i >> 5, d4 = (i & 31) << 2;
        float4 v = *(const float4*)&g_qkv[(size_t)(b * Ss + q0 + r) * (3 * Dd) + h * DHh + d4];
        *(float4*)&Qs[r][d4] = v;
    }

    int q  = tid >> 3;
    int dp = tid & 7;
    float m = -1e30f, l = 0.f;
    u64 acc2[8];
    #pragma unroll
    for (int j = 0; j < 8; j++) acc2[j] = 0ULL;

    const float scale = 0.08838834764831845f;

    for (int kb = 0; kb < Ss; kb += 32) {
        __syncthreads();
        #pragma unroll
        for (int j = 0; j < 4; j++) {
            int i = tid + j * 256;
            int r = i >> 5, d4 = (i & 31) << 2;
            float4 v = *(const float4*)&g_qkv[(size_t)(b * Ss + kb + r) * (3 * Dd) + Dd + h * DHh + d4];
            *(float4*)&KVs[r][d4] = v;
        }
        __syncthreads();
        {
            u64 s2[4] = {0ULL, 0ULL, 0ULL, 0ULL};
            #pragma unroll
            for (int ch = 0; ch < 8; ch++) {
                ulonglong2 qa = *(const ulonglong2*)&Qs[q][ch * 16];
                ulonglong2 qb = *(const ulonglong2*)&Qs[q][ch * 16 + 4];
                ulonglong2 qc = *(const ulonglong2*)&Qs[q][ch * 16 + 8];
                ulonglong2 qd = *(const ulonglong2*)&Qs[q][ch * 16 + 12];
                #pragma unroll
                for (int kk = 0; kk < 4; kk++) {
                    int k = dp + kk * 8;
                    ulonglong2 ka = *(const ulonglong2*)&KVs[k][ch * 16];
                    ulonglong2 kb2 = *(const ulonglong2*)&KVs[k][ch * 16 + 4];
                    ulonglong2 kc = *(const ulonglong2*)&KVs[k][ch * 16 + 8];
                    ulonglong2 kd = *(const ulonglong2*)&KVs[k][ch * 16 + 12];
                    ffma2(s2[kk], qa.x, ka.x);
                    ffma2(s2[kk], qa.y, ka.y);
                    ffma2(s2[kk], qb.x, kb2.x);
                    ffma2(s2[kk], qb.y, kb2.y);
                    ffma2(s2[kk], qc.x, kc.x);
                    ffma2(s2[kk], qc.y, kc.y);
                    ffma2(s2[kk], qd.x, kd.x);
                    ffma2(s2[kk], qd.y, kd.y);
                }
            }
            #pragma unroll
            for (int kk = 0; kk < 4; kk++) {
                float lo, hi; upk2(s2[kk], lo, hi);
                Sc[q][dp + kk * 8] = (lo + hi) * scale;
            }
        }
        __syncthreads();
        #pragma unroll
        for (int j = 0; j < 4; j++) {
            int i = tid + j * 256;
            int r = i >> 5, d4 = (i & 31) << 2;
            float4 v = *(const float4*)&g_qkv[(size_t)(b * Ss + kb + r) * (3 * Dd) + 2 * Dd + h * DHh + d4];
            *(float4*)&KVs[r][d4] = v;
        }
        float sc[32];
        #pragma unroll
        for (int k = 0; k < 32; k++) sc[k] = Sc[q][k];
        float mx = -1e30f;
        #pragma unroll
        for (int k = 0; k < 32; k++) mx = fmaxf(mx, sc[k]);
        float nm = fmaxf(m, mx);
        float corr = __expf(m - nm);
        l *= corr;
        u64 cp = pk2(corr, corr);
        #pragma unroll
        for (int j = 0; j < 8; j++) acc2[j] = fmul2(acc2[j], cp);
        float p[32];
        #pragma unroll
        for (int k = 0; k < 32; k++) { p[k] = __expf(sc[k] - nm); l += p[k]; }
        m = nm;
        __syncthreads();
        #pragma unroll
        for (int k = 0; k < 32; k++) {
            u64 pp = pk2(p[k], p[k]);
            ulonglong2 v0 = *(const ulonglong2*)&KVs[k][dp * 16];
            ulonglong2 v1 = *(const ulonglong2*)&KVs[k][dp * 16 + 4];
            ulonglong2 v2 = *(const ulonglong2*)&KVs[k][dp * 16 + 8];
            ulonglong2 v3 = *(const ulonglong2*)&KVs[k][dp * 16 + 12];
            ffma2(acc2[0], pp, v0.x);
            ffma2(acc2[1], pp, v0.y);
            ffma2(acc2[2], pp, v1.x);
            ffma2(acc2[3], pp, v1.y);
            ffma2(acc2[4], pp, v2.x);
            ffma2(acc2[5], pp, v2.y);
            ffma2(acc2[6], pp, v3.x);
            ffma2(acc2[7], pp, v3.y);
        }
    }
    float inv = 1.f / l;
    int t = b * Ss + q0 + q;
    float* op = g_attn + (size_t)t * Dd + h * DHh + dp * 16;
    float o[16];
    upk2(acc2[0], o[0],  o[1]);   upk2(acc2[1], o[2],  o[3]);
    upk2(acc2[2], o[4],  o[5]);   upk2(acc2[3], o[6],  o[7]);
    upk2(acc2[4], o[8],  o[9]);   upk2(acc2[5], o[10], o[11]);
    upk2(acc2[6], o[12], o[13]);  upk2(acc2[7], o[14], o[15]);
    #pragma unroll
    for (int j = 0; j < 16; j++) op[j] = o[j] * inv;
}

// ---------------- gate ------------------------------------------------------
__global__ void k_gate(const float* __restrict__ wg) {
    int warp = threadIdx.x >> 5;
    int lane = threadIdx.x & 31;
    int t = blockIdx.x * 8 + warp;
    __shared__ float bsum[NE];
    if (threadIdx.x < NE) bsum[threadIdx.x] = 0.f;
    __syncthreads();

    float lg[16];
    #pragma unroll
    for (int e = 0; e < 16; e++) lg[e] = 0.f;
    const float* row = g_xn + (size_t)t * Dd;
    for (int d = lane; d < Dd; d += 32) {
        float x = row[d];
        const float* w = wg + (size_t)d * NE;
        #pragma unroll
        for (int e = 0; e < 16; e++) lg[e] += x * w[e];
    }
    #pragma unroll
    for (int e = 0; e < 16; e++)
        #pragma unroll
        for (int o = 16; o; o >>= 1) lg[e] += __shfl_xor_sync(0xffffffffu, lg[e], o);

    float mx = lg[0];
    #pragma unroll
    for (int e = 1; e < 16; e++) mx = fmaxf(mx, lg[e]);
    float pe[16]; float se = 0.f;
    #pragma unroll
    for (int e = 0; e < 16; e++) { pe[e] = __expf(lg[e] - mx); se += pe[e]; }
    float inv = 1.f / se;

    if (lane == 0) {
        int be = 0; float bl = lg[0];
        #pragma unroll
        for (int e = 1; e < 16; e++) if (lg[e] > bl) { bl = lg[e]; be = e; }
        g_expert[t] = be;
        g_prob[t] = pe[be] * inv;
        #pragma unroll
        for (int e = 0; e < 16; e++) atomicAdd(&bsum[e], pe[e] * inv);
    }
    __syncthreads();
    if (threadIdx.x < NE) atomicAdd(&g_probsum[threadIdx.x], bsum[threadIdx.x]);
}

// ---------------- routing ---------------------------------------------------
__global__ void k_route() {
    __shared__ int sh_e[Tt];
    __shared__ int cnts[256][NE];
    __shared__ int tot[NE];
    int tid = threadIdx.x;
    for (int i = tid; i < Tt; i += 256) sh_e[i] = g_expert[i];
    #pragma unroll
    for (int e = 0; e < NE; e++) cnts[tid][e] = 0;
    __syncthreads();
    for (int i = 0; i < 8; i++) {
        int e = sh_e[tid * 8 + i];
        cnts[tid][e]++;
    }
    __syncthreads();
    if (tid < NE) {
        int run = 0;
        for (int i = 0; i < 256; i++) {
            int c = cnts[i][tid];
            cnts[i][tid] = run;
            run += c;
        }
        tot[tid] = run;
        g_cnt[tid] = (run < CAPe) ? run : CAPe;
    }
    __syncthreads();
    for (int i = 0; i < 8; i++) {
        int t = tid * 8 + i;
        int e = sh_e[t];
        int r = cnts[tid][e]++;
        if (r < CAPe) g_tok[e * CAPe + r] = t;
    }
    if (tid == 0) {
        float a = 0.f;
        for (int e = 0; e < NE; e++) a += (float)tot[e] * g_probsum[e];
        g_aux += a * ((float)NE / ((float)Tt * (float)Tt));
    }
}

// ---------------- output ----------------------------------------------------
__global__ void k_out(float* __restrict__ out, int n) {
    int idx = blockIdx.x * 256 + threadIdx.x;
    if (idx < n) {
        if (idx < Tt * Dd) out[idx] = g_x[idx];
        else out[idx] = g_aux;
    }
}

// ---------------- launch ----------------------------------------------------
extern "C" void kernel_launch(void* const* d_in, const int* in_sizes, int n_in,
                              void* d_out, int out_size) {
    const int*   tokens = (const int*)d_in[0];
    const float* emb    = (const float*)d_in[1];
    const float* w_qkv  = (const float*)d_in[2];
    const float* b_qkv  = (const float*)d_in[3];
    const float* w_out  = (const float*)d_in[4];
    const float* b_out  = (const float*)d_in[5];
    const float* attn_g = (const float*)d_in[6];
    const float* attn_b = (const float*)d_in[7];
    const float* moe_g  = (const float*)d_in[8];
    const float* moe_b  = (const float*)d_in[9];
    const float* w_gate = (const float*)d_in[10];
    const float* w_exp  = (const float*)d_in[11];
    const float* b_exp  = (const float*)d_in[12];

    float *px, *pxn, *pqkv, *pattn;
    cudaGetSymbolAddress((void**)&px, g_x);
    cudaGetSymbolAddress((void**)&pxn, g_xn);
    cudaGetSymbolAddress((void**)&pqkv, g_qkv);
    cudaGetSymbolAddress((void**)&pattn, g_attn);

    cudaFuncSetAttribute(k_gemm_mma, cudaFuncAttributeMaxDynamicSharedMemorySize, MMA_SMEM_BYTES);
    cudaFuncSetAttribute(k_moe_mma, cudaFuncAttributeMaxDynamicSharedMemorySize, MMA_SMEM_BYTES);

    k_init<<<1, 1>>>();
    k_embed<<<(Tt * Dd) / 256, 256>>>(tokens, emb);

    for (int l = 0; l < Ll; l++) {
        k_ln<<<Tt, 256>>>(attn_g + (size_t)l * Dd, attn_b + (size_t)l * Dd);
        k_gemm_mma<<<dim3((3 * Dd) / 64, Tt / 128), 256, MMA_SMEM_BYTES>>>(
            pxn, w_qkv, b_qkv, nullptr, pqkv, 3 * Dd, Dd);
        k_attn<<<dim3(Bb * Hh, Ss / 32), 256>>>();
        k_gemm_mma<<<dim3(Dd / 64, Tt / 128), 256, MMA_SMEM_BYTES>>>(
            pattn, w_out, b_out, px, px, Dd, Dd);
        k_ln<<<Tt, 256>>>(moe_g + (size_t)l * Dd, moe_b + (size_t)l * Dd);
        k_zero16<<<1, 16>>>();
        k_gate<<<Tt / 8, 256>>>(w_gate);
        k_route<<<1, 256>>>();
        k_moe_mma<<<dim3(Dd / 64, (CAPe + 127) / 128, NE), 256, MMA_SMEM_BYTES>>>(w_exp, b_exp);
    }

    k_out<<<(out_size + 255) / 256, 256>>>((float*)d_out, out_size);
}